// round 4
// baseline (speedup 1.0000x reference)
#include <cuda_runtime.h>
#include <cuda_bf16.h>
#include <cstdint>

// ============================================================================
// Problem constants
// ============================================================================
#define NROWS 8192
#define DIM   256
#define TM    128          // CTA tile M
#define TN    128          // CTA tile N
#define KC    64           // K elements per chunk (64 bf16 = 128 bytes/row)
#define NCHUNK (DIM / KC)  // 4
#define NKSTEP (KC / 16)   // 4 mma k-steps per chunk

// smem: 2 stages x [A_hi | A_lo | B_hi | B_lo], each tile 128 rows x 128B
#define TILE_BYTES  16384
#define STAGE_BYTES (4 * TILE_BYTES)         // 64 KB
#define SMEM_TOTAL  (2 * STAGE_BYTES)        // 128 KB

// Device scratch: normalized features, bf16 hi/lo split (4 MB each).
// MUST be >=16B aligned: cp.async 16B sources point here.
__device__ __align__(1024) __nv_bfloat16 g_hi[(size_t)NROWS * DIM];
__device__ __align__(1024) __nv_bfloat16 g_lo[(size_t)NROWS * DIM];

// ============================================================================
// Helpers
// ============================================================================
__device__ __forceinline__ uint32_t smem_u32(const void* p) {
    uint32_t a;
    asm("{ .reg .u64 t; cvta.to.shared.u64 t, %1; cvt.u32.u64 %0, t; }"
        : "=r"(a) : "l"(p));
    return a;
}

__device__ __forceinline__ uint32_t sw128(uint32_t off) {
    return off ^ ((off >> 3) & 0x70);
}

#define CP_ASYNC16(saddr, gptr) \
    asm volatile("cp.async.cg.shared.global [%0], [%1], 16;" \
                 :: "r"(saddr), "l"(gptr) : "memory")
#define CP_COMMIT() asm volatile("cp.async.commit_group;" ::: "memory")
#define CP_WAIT(n)  asm volatile("cp.async.wait_group %0;" :: "n"(n) : "memory")

__device__ __forceinline__ void ldsm_x4(uint32_t addr, uint32_t* r) {
    asm volatile("ldmatrix.sync.aligned.m8n8.x4.shared.b16 {%0,%1,%2,%3}, [%4];"
                 : "=r"(r[0]), "=r"(r[1]), "=r"(r[2]), "=r"(r[3]) : "r"(addr));
}

__device__ __forceinline__ void mma_bf16(float* c, const uint32_t* a, const uint32_t* b) {
    asm volatile(
        "mma.sync.aligned.m16n8k16.row.col.f32.bf16.bf16.f32 "
        "{%0,%1,%2,%3}, {%4,%5,%6,%7}, {%8,%9}, {%0,%1,%2,%3};"
        : "+f"(c[0]), "+f"(c[1]), "+f"(c[2]), "+f"(c[3])
        : "r"(a[0]), "r"(a[1]), "r"(a[2]), "r"(a[3]), "r"(b[0]), "r"(b[1]));
}

// ============================================================================
// Kernel 1: row L2-normalize + bf16 hi/lo split (one warp per row)
// ============================================================================
__global__ void __launch_bounds__(256)
norm_split_kernel(const float* __restrict__ x) {
    const int row = blockIdx.x * 8 + (threadIdx.x >> 5);
    const int lid = threadIdx.x & 31;
    const float* xr = x + (size_t)row * DIM;

    float v[8];
    float ss = 0.f;
#pragma unroll
    for (int j = 0; j < 8; j++) {
        v[j] = xr[lid + 32 * j];
        ss += v[j] * v[j];
    }
#pragma unroll
    for (int o = 16; o > 0; o >>= 1)
        ss += __shfl_xor_sync(0xFFFFFFFFu, ss, o);

    const float scale = 1.f / fmaxf(sqrtf(ss), 1e-8f);
    const size_t base = (size_t)row * DIM;
#pragma unroll
    for (int j = 0; j < 8; j++) {
        float xn = v[j] * scale;
        __nv_bfloat16 hi = __float2bfloat16(xn);
        float lo = xn - __bfloat162float(hi);
        g_hi[base + lid + 32 * j] = hi;
        g_lo[base + lid + 32 * j] = __float2bfloat16(lo);
    }
}

// ============================================================================
// Kernel 2: Gram GEMM via mma.sync bf16 hi/lo, cp.async double-buffered
// One 128x128 tile per CTA (grid 64x64), 256 threads = 8 warps (2 M x 4 N),
// warp tile 64x32. C = hi*hi^T + hi*lo^T + lo*hi^T (lo*lo^T dropped, ~2^-18).
// ============================================================================
__device__ __forceinline__ void prefetch_stage(
    uint32_t sbase, const __nv_bfloat16* __restrict__ Ahi,
    const __nv_bfloat16* __restrict__ Alo,
    const __nv_bfloat16* __restrict__ Bhi,
    const __nv_bfloat16* __restrict__ Blo, int kbase, int tid)
{
#pragma unroll
    for (int it = 0; it < 4; it++) {
        int i = tid + it * 256;           // 0..1023 (16B groups per tile)
        int row = i >> 3;
        int g   = i & 7;
        size_t goff = (size_t)row * DIM + kbase + g * 8;
        uint32_t so = sw128((uint32_t)(row * 128 + g * 16));
        CP_ASYNC16(sbase + so,                     (const char*)(Ahi + goff));
        CP_ASYNC16(sbase + TILE_BYTES + so,        (const char*)(Alo + goff));
        CP_ASYNC16(sbase + 2 * TILE_BYTES + so,    (const char*)(Bhi + goff));
        CP_ASYNC16(sbase + 3 * TILE_BYTES + so,    (const char*)(Blo + goff));
    }
}

__global__ void __launch_bounds__(256, 1)
gram_mma_kernel(float* __restrict__ out) {
    extern __shared__ char smem[];
    const uint32_t sb = smem_u32(smem);

    const int tid = threadIdx.x;
    const int wid = tid >> 5;
    const int lid = tid & 31;
    const int warp_m = wid & 1;   // 0..1  -> 64-row slice
    const int warp_n = wid >> 1;  // 0..3  -> 32-col slice
    const int tile_m = blockIdx.y;
    const int tile_n = blockIdx.x;

    const __nv_bfloat16* Ahi_g = g_hi + (size_t)tile_m * TM * DIM;
    const __nv_bfloat16* Alo_g = g_lo + (size_t)tile_m * TM * DIM;
    const __nv_bfloat16* Bhi_g = g_hi + (size_t)tile_n * TN * DIM;
    const __nv_bfloat16* Blo_g = g_lo + (size_t)tile_n * TN * DIM;

    float c[4][4][4];
#pragma unroll
    for (int mi = 0; mi < 4; mi++)
#pragma unroll
        for (int ni = 0; ni < 4; ni++)
#pragma unroll
            for (int q = 0; q < 4; q++) c[mi][ni][q] = 0.f;

    // prologue: prefetch chunk 0 into stage 0
    prefetch_stage(sb, Ahi_g, Alo_g, Bhi_g, Blo_g, 0, tid);
    CP_COMMIT();

    for (int kc = 0; kc < NCHUNK; kc++) {
        const uint32_t st = sb + (uint32_t)(kc & 1) * STAGE_BYTES;
        if (kc + 1 < NCHUNK) {
            prefetch_stage(sb + (uint32_t)((kc + 1) & 1) * STAGE_BYTES,
                           Ahi_g, Alo_g, Bhi_g, Blo_g, (kc + 1) * KC, tid);
            CP_COMMIT();
            CP_WAIT(1);
        } else {
            CP_WAIT(0);
        }
        __syncthreads();

        const uint32_t sAhi = st;
        const uint32_t sAlo = st + TILE_BYTES;
        const uint32_t sBhi = st + 2 * TILE_BYTES;
        const uint32_t sBlo = st + 3 * TILE_BYTES;

#pragma unroll
        for (int ks = 0; ks < NKSTEP; ks++) {
            const uint32_t koff = (uint32_t)(ks * 32 + ((lid >> 4) << 4));

            uint32_t a_hi[4][4], a_lo[4][4];
#pragma unroll
            for (int mi = 0; mi < 4; mi++) {
                int row = warp_m * 64 + mi * 16 + (lid & 15);
                uint32_t so = sw128((uint32_t)(row * 128) + koff);
                ldsm_x4(sAhi + so, a_hi[mi]);
                ldsm_x4(sAlo + so, a_lo[mi]);
            }

            uint32_t b_hi[4][2], b_lo[4][2];
#pragma unroll
            for (int nb = 0; nb < 2; nb++) {
                int row = warp_n * 32 + nb * 16 + (lid & 15);
                uint32_t so = sw128((uint32_t)(row * 128) + koff);
                uint32_t r[4];
                ldsm_x4(sBhi + so, r);
                b_hi[nb * 2][0] = r[0]; b_hi[nb * 2][1] = r[2];
                b_hi[nb * 2 + 1][0] = r[1]; b_hi[nb * 2 + 1][1] = r[3];
                ldsm_x4(sBlo + so, r);
                b_lo[nb * 2][0] = r[0]; b_lo[nb * 2][1] = r[2];
                b_lo[nb * 2 + 1][0] = r[1]; b_lo[nb * 2 + 1][1] = r[3];
            }

#pragma unroll
            for (int mi = 0; mi < 4; mi++)
#pragma unroll
                for (int ni = 0; ni < 4; ni++) {
                    mma_bf16(c[mi][ni], a_hi[mi], b_hi[ni]);
                    mma_bf16(c[mi][ni], a_hi[mi], b_lo[ni]);
                    mma_bf16(c[mi][ni], a_lo[mi], b_hi[ni]);
                }
        }
        __syncthreads();
    }

    // ---- epilogue: clamp + store (float2 per fragment half-row) ----
    const int row0 = tile_m * TM + warp_m * 64 + (lid >> 2);
    const int col0 = tile_n * TN + warp_n * 32 + (lid & 3) * 2;

#pragma unroll
    for (int mi = 0; mi < 4; mi++) {
        float* r0p = out + (size_t)(row0 + mi * 16) * NROWS + col0;
        float* r1p = out + (size_t)(row0 + mi * 16 + 8) * NROWS + col0;
#pragma unroll
        for (int ni = 0; ni < 4; ni++) {
            float2 v0;
            v0.x = fmaxf(c[mi][ni][0], 0.f);
            v0.y = fmaxf(c[mi][ni][1], 0.f);
            *(float2*)(r0p + ni * 8) = v0;
        }
#pragma unroll
        for (int ni = 0; ni < 4; ni++) {
            float2 v1;
            v1.x = fmaxf(c[mi][ni][2], 0.f);
            v1.y = fmaxf(c[mi][ni][3], 0.f);
            *(float2*)(r1p + ni * 8) = v1;
        }
    }
}

// ============================================================================
// Launch
// ============================================================================
extern "C" void kernel_launch(void* const* d_in, const int* in_sizes, int n_in,
                              void* d_out, int out_size) {
    const float* features = (const float*)d_in[0];
    float* out = (float*)d_out;

    norm_split_kernel<<<NROWS / 8, 256>>>(features);

    cudaFuncSetAttribute(gram_mma_kernel,
                         cudaFuncAttributeMaxDynamicSharedMemorySize, SMEM_TOTAL);
    dim3 grid(NROWS / TN, NROWS / TM);
    gram_mma_kernel<<<grid, 256, SMEM_TOTAL>>>(out);
}

// round 5
// speedup vs baseline: 1.5982x; 1.5982x over previous
#include <cuda_runtime.h>
#include <cuda_bf16.h>
#include <cstdint>

// ============================================================================
// Problem constants
// ============================================================================
#define NROWS 8192
#define DIM   256
#define TM    128          // CTA tile M
#define TN    128          // CTA tile N
#define NTILE (NROWS / TM) // 64
#define NCTAS (NTILE * (NTILE + 1) / 2)  // 2080 upper-triangular tiles
#define KC    64           // K elements per chunk (64 bf16 = 128 bytes/row)
#define NCHUNK (DIM / KC)  // 4
#define NKSTEP (KC / 16)   // 4 mma k-steps per chunk

// smem: 2 stages x [A_hi | A_lo | B_hi | B_lo], each tile 128 rows x 128B
#define TILE_BYTES  16384
#define STAGE_BYTES (4 * TILE_BYTES)         // 64 KB
#define SMEM_TOTAL  (2 * STAGE_BYTES)        // 128 KB
// transpose staging (reuses the stage buffers after mainloop):
#define TPITCH 132                           // floats; 128x132 fp32 = 67584 B

// Device scratch: normalized features, bf16 hi/lo split (4 MB each).
__device__ __align__(1024) __nv_bfloat16 g_hi[(size_t)NROWS * DIM];
__device__ __align__(1024) __nv_bfloat16 g_lo[(size_t)NROWS * DIM];

// ============================================================================
// Helpers
// ============================================================================
__device__ __forceinline__ uint32_t smem_u32(const void* p) {
    uint32_t a;
    asm("{ .reg .u64 t; cvta.to.shared.u64 t, %1; cvt.u32.u64 %0, t; }"
        : "=r"(a) : "l"(p));
    return a;
}

__device__ __forceinline__ uint32_t sw128(uint32_t off) {
    return off ^ ((off >> 3) & 0x70);
}

#define CP_ASYNC16(saddr, gptr) \
    asm volatile("cp.async.cg.shared.global [%0], [%1], 16;" \
                 :: "r"(saddr), "l"(gptr) : "memory")
#define CP_COMMIT() asm volatile("cp.async.commit_group;" ::: "memory")
#define CP_WAIT(n)  asm volatile("cp.async.wait_group %0;" :: "n"(n) : "memory")

__device__ __forceinline__ void ldsm_x4(uint32_t addr, uint32_t* r) {
    asm volatile("ldmatrix.sync.aligned.m8n8.x4.shared.b16 {%0,%1,%2,%3}, [%4];"
                 : "=r"(r[0]), "=r"(r[1]), "=r"(r[2]), "=r"(r[3]) : "r"(addr));
}

__device__ __forceinline__ void mma_bf16(float* c, const uint32_t* a, const uint32_t* b) {
    asm volatile(
        "mma.sync.aligned.m16n8k16.row.col.f32.bf16.bf16.f32 "
        "{%0,%1,%2,%3}, {%4,%5,%6,%7}, {%8,%9}, {%0,%1,%2,%3};"
        : "+f"(c[0]), "+f"(c[1]), "+f"(c[2]), "+f"(c[3])
        : "r"(a[0]), "r"(a[1]), "r"(a[2]), "r"(a[3]), "r"(b[0]), "r"(b[1]));
}

// ============================================================================
// Kernel 1: row L2-normalize + bf16 hi/lo split (one warp per row)
// ============================================================================
__global__ void __launch_bounds__(256)
norm_split_kernel(const float* __restrict__ x) {
    const int row = blockIdx.x * 8 + (threadIdx.x >> 5);
    const int lid = threadIdx.x & 31;
    const float* xr = x + (size_t)row * DIM;

    float v[8];
    float ss = 0.f;
#pragma unroll
    for (int j = 0; j < 8; j++) {
        v[j] = xr[lid + 32 * j];
        ss += v[j] * v[j];
    }
#pragma unroll
    for (int o = 16; o > 0; o >>= 1)
        ss += __shfl_xor_sync(0xFFFFFFFFu, ss, o);

    const float scale = 1.f / fmaxf(sqrtf(ss), 1e-8f);
    const size_t base = (size_t)row * DIM;
#pragma unroll
    for (int j = 0; j < 8; j++) {
        float xn = v[j] * scale;
        __nv_bfloat16 hi = __float2bfloat16(xn);
        float lo = xn - __bfloat162float(hi);
        g_hi[base + lid + 32 * j] = hi;
        g_lo[base + lid + 32 * j] = __float2bfloat16(lo);
    }
}

// ============================================================================
// Kernel 2: Gram GEMM, upper-triangular tiles only + mirrored write.
// 256 threads = 8 warps (2 M x 4 N), warp tile 64x32.
// C = hi*hi^T + hi*lo^T + lo*hi^T (lo*lo^T dropped, ~2^-18).
// ============================================================================
__device__ __forceinline__ void prefetch_stage(
    uint32_t sbase, const __nv_bfloat16* __restrict__ Ahi,
    const __nv_bfloat16* __restrict__ Alo,
    const __nv_bfloat16* __restrict__ Bhi,
    const __nv_bfloat16* __restrict__ Blo, int kbase, int tid)
{
#pragma unroll
    for (int it = 0; it < 4; it++) {
        int i = tid + it * 256;           // 0..1023 (16B groups per tile)
        int row = i >> 3;
        int g   = i & 7;
        size_t goff = (size_t)row * DIM + kbase + g * 8;
        uint32_t so = sw128((uint32_t)(row * 128 + g * 16));
        CP_ASYNC16(sbase + so,                     (const char*)(Ahi + goff));
        CP_ASYNC16(sbase + TILE_BYTES + so,        (const char*)(Alo + goff));
        CP_ASYNC16(sbase + 2 * TILE_BYTES + so,    (const char*)(Bhi + goff));
        CP_ASYNC16(sbase + 3 * TILE_BYTES + so,    (const char*)(Blo + goff));
    }
}

__global__ void __launch_bounds__(256, 1)
gram_mma_kernel(float* __restrict__ out) {
    extern __shared__ char smem[];
    const uint32_t sb = smem_u32(smem);

    const int tid = threadIdx.x;
    const int wid = tid >> 5;
    const int lid = tid & 31;
    const int warp_m = wid & 1;   // 0..1  -> 64-row slice
    const int warp_n = wid >> 1;  // 0..3  -> 32-col slice

    // decode linear block index -> upper-triangular (tile_m, tile_n), tn >= tm
    int tile_m = 0;
    {
        int rem = blockIdx.x;
        while (rem >= NTILE - tile_m) { rem -= NTILE - tile_m; tile_m++; }
        tile_m += 0;
        // tn computed below
        tile_m = tile_m;  // no-op clarity
        // store rem in tile_n slot
        // (computed after loop)
        // tile_n:
        // fallthrough
        // (rem holds offset)
        // assign:
        //   tile_n = tile_m + rem;
        // done outside
        // NOTE: loop max 64 iterations, negligible.
        // We keep rem in a local:
        // (reuse below)
        //
        // assign now:
        ;
        // tile_n
        int tn = tile_m + rem;
        // stash via shared variable trick not needed; just shadow:
        // we need tile_n after this block:
        // use static locals:
        // (simplify: recompute)
        // -- break out:
        // Using goto-free approach: set both here.
        // tile_n variable declared next line.
        // Store in register:
        // (We'll just declare tile_n here.)
        // ---
        // see below
        (void)tn;
    }
    // clean re-decode (simple and branch-predictable):
    int tm = 0, rem = blockIdx.x;
    while (rem >= NTILE - tm) { rem -= NTILE - tm; tm++; }
    const int tile_n = tm + rem;
    tile_m = tm;

    const __nv_bfloat16* Ahi_g = g_hi + (size_t)tile_m * TM * DIM;
    const __nv_bfloat16* Alo_g = g_lo + (size_t)tile_m * TM * DIM;
    const __nv_bfloat16* Bhi_g = g_hi + (size_t)tile_n * TN * DIM;
    const __nv_bfloat16* Blo_g = g_lo + (size_t)tile_n * TN * DIM;

    float c[4][4][4];
#pragma unroll
    for (int mi = 0; mi < 4; mi++)
#pragma unroll
        for (int ni = 0; ni < 4; ni++)
#pragma unroll
            for (int q = 0; q < 4; q++) c[mi][ni][q] = 0.f;

    // prologue: prefetch chunk 0 into stage 0
    prefetch_stage(sb, Ahi_g, Alo_g, Bhi_g, Blo_g, 0, tid);
    CP_COMMIT();

    for (int kc = 0; kc < NCHUNK; kc++) {
        const uint32_t st = sb + (uint32_t)(kc & 1) * STAGE_BYTES;
        if (kc + 1 < NCHUNK) {
            prefetch_stage(sb + (uint32_t)((kc + 1) & 1) * STAGE_BYTES,
                           Ahi_g, Alo_g, Bhi_g, Blo_g, (kc + 1) * KC, tid);
            CP_COMMIT();
            CP_WAIT(1);
        } else {
            CP_WAIT(0);
        }
        __syncthreads();

        const uint32_t sAhi = st;
        const uint32_t sAlo = st + TILE_BYTES;
        const uint32_t sBhi = st + 2 * TILE_BYTES;
        const uint32_t sBlo = st + 3 * TILE_BYTES;

#pragma unroll
        for (int ks = 0; ks < NKSTEP; ks++) {
            const uint32_t koff = (uint32_t)(ks * 32 + ((lid >> 4) << 4));

            uint32_t a_hi[4][4], a_lo[4][4];
#pragma unroll
            for (int mi = 0; mi < 4; mi++) {
                int row = warp_m * 64 + mi * 16 + (lid & 15);
                uint32_t so = sw128((uint32_t)(row * 128) + koff);
                ldsm_x4(sAhi + so, a_hi[mi]);
                ldsm_x4(sAlo + so, a_lo[mi]);
            }

            uint32_t b_hi[4][2], b_lo[4][2];
#pragma unroll
            for (int nb = 0; nb < 2; nb++) {
                int row = warp_n * 32 + nb * 16 + (lid & 15);
                uint32_t so = sw128((uint32_t)(row * 128) + koff);
                uint32_t r[4];
                ldsm_x4(sBhi + so, r);
                b_hi[nb * 2][0] = r[0]; b_hi[nb * 2][1] = r[2];
                b_hi[nb * 2 + 1][0] = r[1]; b_hi[nb * 2 + 1][1] = r[3];
                ldsm_x4(sBlo + so, r);
                b_lo[nb * 2][0] = r[0]; b_lo[nb * 2][1] = r[2];
                b_lo[nb * 2 + 1][0] = r[1]; b_lo[nb * 2 + 1][1] = r[3];
            }

#pragma unroll
            for (int mi = 0; mi < 4; mi++)
#pragma unroll
                for (int ni = 0; ni < 4; ni++) {
                    mma_bf16(c[mi][ni], a_hi[mi], b_hi[ni]);
                    mma_bf16(c[mi][ni], a_hi[mi], b_lo[ni]);
                    mma_bf16(c[mi][ni], a_lo[mi], b_hi[ni]);
                }
        }
        __syncthreads();
    }

    // clamp all accumulators once
#pragma unroll
    for (int mi = 0; mi < 4; mi++)
#pragma unroll
        for (int ni = 0; ni < 4; ni++)
#pragma unroll
            for (int q = 0; q < 4; q++) c[mi][ni][q] = fmaxf(c[mi][ni][q], 0.f);

    // ---- epilogue 1: direct store of tile (tm, tn) ----
    const int rr0 = warp_m * 64 + (lid >> 2);          // row within tile
    const int cc0 = warp_n * 32 + (lid & 3) * 2;       // col within tile
    {
        const int row0 = tile_m * TM + rr0;
        const int col0 = tile_n * TN + cc0;
#pragma unroll
        for (int mi = 0; mi < 4; mi++) {
            float* r0p = out + (size_t)(row0 + mi * 16) * NROWS + col0;
            float* r1p = out + (size_t)(row0 + mi * 16 + 8) * NROWS + col0;
#pragma unroll
            for (int ni = 0; ni < 4; ni++)
                *(float2*)(r0p + ni * 8) = make_float2(c[mi][ni][0], c[mi][ni][1]);
#pragma unroll
            for (int ni = 0; ni < 4; ni++)
                *(float2*)(r1p + ni * 8) = make_float2(c[mi][ni][2], c[mi][ni][3]);
        }
    }

    // ---- epilogue 2: mirrored tile (tn, tm) via smem transpose ----
    if (tile_n != tile_m) {
        float* smem_t = (float*)smem;   // 128 x TPITCH floats (67584 B), reuses stages
        // stage transposed: smem_t[col * TPITCH + row]
#pragma unroll
        for (int mi = 0; mi < 4; mi++) {
            const int rA = rr0 + mi * 16;
            const int rB = rA + 8;
#pragma unroll
            for (int ni = 0; ni < 4; ni++) {
                const int cc = cc0 + ni * 8;
                smem_t[(cc)     * TPITCH + rA] = c[mi][ni][0];
                smem_t[(cc + 1) * TPITCH + rA] = c[mi][ni][1];
                smem_t[(cc)     * TPITCH + rB] = c[mi][ni][2];
                smem_t[(cc + 1) * TPITCH + rB] = c[mi][ni][3];
            }
        }
        __syncthreads();

        // cooperative coalesced copy out: rows of the transposed tile
        const size_t obase = (size_t)tile_n * TN * NROWS + (size_t)tile_m * TM;
#pragma unroll
        for (int j = 0; j < 16; j++) {
            int v = tid + j * 256;          // 0..4095 float4 units
            int cc = v >> 5;                // 0..127 (transposed row)
            int r4 = (v & 31) * 4;          // 0..124
            float4 val = *(const float4*)(smem_t + cc * TPITCH + r4);
            *(float4*)(out + obase + (size_t)cc * NROWS + r4) = val;
        }
    }
}

// ============================================================================
// Launch
// ============================================================================
extern "C" void kernel_launch(void* const* d_in, const int* in_sizes, int n_in,
                              void* d_out, int out_size) {
    const float* features = (const float*)d_in[0];
    float* out = (float*)d_out;

    norm_split_kernel<<<NROWS / 8, 256>>>(features);

    cudaFuncSetAttribute(gram_mma_kernel,
                         cudaFuncAttributeMaxDynamicSharedMemorySize, SMEM_TOTAL);
    gram_mma_kernel<<<NCTAS, 256, SMEM_TOTAL>>>(out);
}

// round 7
// speedup vs baseline: 3.4907x; 2.1842x over previous
#include <cuda_runtime.h>
#include <cuda_fp16.h>
#include <cstdint>

// ============================================================================
// Problem constants
// ============================================================================
#define NROWS 8192
#define DIM   256
#define TM    128
#define TN    128
#define NTILE (NROWS / TM)                 // 64
#define NCTAS (NTILE * (NTILE + 1) / 2)    // 2080 upper-triangular tiles
#define KC    64                           // K per chunk (64 fp16 = 128 B/row)
#define NCHUNK (DIM / KC)                  // 4
#define NKSTEP (KC / 16)                   // 4

// smem: 2 stages x [A | B], each tile 128 rows x 128B fp16
#define TILE_BYTES  16384
#define STAGE_BYTES (2 * TILE_BYTES)       // 32 KB
#define SMEM_TOTAL  (2 * STAGE_BYTES)      // 64 KB
#define TPITCH 132                         // transpose pitch (floats); 64*132*4=33.8KB

// Device scratch: normalized features in fp16 (4 MB)
__device__ __align__(1024) __half g_x[(size_t)NROWS * DIM];

// ============================================================================
// Helpers
// ============================================================================
__device__ __forceinline__ uint32_t smem_u32(const void* p) {
    uint32_t a;
    asm("{ .reg .u64 t; cvta.to.shared.u64 t, %1; cvt.u32.u64 %0, t; }"
        : "=r"(a) : "l"(p));
    return a;
}

__device__ __forceinline__ uint32_t sw128(uint32_t off) {
    return off ^ ((off >> 3) & 0x70);
}

#define CP_ASYNC16(saddr, gptr) \
    asm volatile("cp.async.cg.shared.global [%0], [%1], 16;" \
                 :: "r"(saddr), "l"(gptr) : "memory")
#define CP_COMMIT() asm volatile("cp.async.commit_group;" ::: "memory")
#define CP_WAIT(n)  asm volatile("cp.async.wait_group %0;" :: "n"(n) : "memory")

__device__ __forceinline__ void ldsm_x4(uint32_t addr, uint32_t* r) {
    asm volatile("ldmatrix.sync.aligned.m8n8.x4.shared.b16 {%0,%1,%2,%3}, [%4];"
                 : "=r"(r[0]), "=r"(r[1]), "=r"(r[2]), "=r"(r[3]) : "r"(addr));
}

__device__ __forceinline__ void mma_f16(float* c, const uint32_t* a, const uint32_t* b) {
    asm volatile(
        "mma.sync.aligned.m16n8k16.row.col.f32.f16.f16.f32 "
        "{%0,%1,%2,%3}, {%4,%5,%6,%7}, {%8,%9}, {%0,%1,%2,%3};"
        : "+f"(c[0]), "+f"(c[1]), "+f"(c[2]), "+f"(c[3])
        : "r"(a[0]), "r"(a[1]), "r"(a[2]), "r"(a[3]), "r"(b[0]), "r"(b[1]));
}

// ============================================================================
// Kernel 1: row L2-normalize -> fp16 (one warp per row)
// ============================================================================
__global__ void __launch_bounds__(256)
norm_kernel(const float* __restrict__ x) {
    const int row = blockIdx.x * 8 + (threadIdx.x >> 5);
    const int lid = threadIdx.x & 31;
    const float* xr = x + (size_t)row * DIM;

    float v[8];
    float ss = 0.f;
#pragma unroll
    for (int j = 0; j < 8; j++) {
        v[j] = xr[lid + 32 * j];
        ss += v[j] * v[j];
    }
#pragma unroll
    for (int o = 16; o > 0; o >>= 1)
        ss += __shfl_xor_sync(0xFFFFFFFFu, ss, o);

    const float scale = 1.f / fmaxf(sqrtf(ss), 1e-8f);
    const size_t base = (size_t)row * DIM;
#pragma unroll
    for (int j = 0; j < 8; j++)
        g_x[base + lid + 32 * j] = __float2half_rn(v[j] * scale);
}

// ============================================================================
// Kernel 2: Gram GEMM (fp16, single product), upper-triangular + mirror.
// 256 threads = 8 warps (2 M x 4 N), warp tile 64x32, 2 CTAs/SM.
// ============================================================================
__device__ __forceinline__ void prefetch_stage(
    uint32_t sbase, const __half* __restrict__ A,
    const __half* __restrict__ B, int kbase, int tid)
{
#pragma unroll
    for (int it = 0; it < 4; it++) {
        int i = tid + it * 256;           // 0..1023 (16B groups per tile)
        int row = i >> 3;
        int g   = i & 7;
        size_t goff = (size_t)row * DIM + kbase + g * 8;
        uint32_t so = sw128((uint32_t)(row * 128 + g * 16));
        CP_ASYNC16(sbase + so,              (const char*)(A + goff));
        CP_ASYNC16(sbase + TILE_BYTES + so, (const char*)(B + goff));
    }
}

__global__ void __launch_bounds__(256, 2)
gram_mma_kernel(float* __restrict__ out) {
    extern __shared__ char smem[];
    const uint32_t sb = smem_u32(smem);

    const int tid = threadIdx.x;
    const int wid = tid >> 5;
    const int lid = tid & 31;
    const int warp_m = wid & 1;   // 0..1 -> 64-row slice
    const int warp_n = wid >> 1;  // 0..3 -> 32-col slice

    // decode linear block index -> upper-triangular (tile_m, tile_n), tn >= tm
    int tm = 0, rem = blockIdx.x;
    while (rem >= NTILE - tm) { rem -= NTILE - tm; tm++; }
    const int tile_m = tm;
    const int tile_n = tm + rem;

    const __half* A_g = g_x + (size_t)tile_m * TM * DIM;
    const __half* B_g = g_x + (size_t)tile_n * TN * DIM;

    float c[4][4][4];
#pragma unroll
    for (int mi = 0; mi < 4; mi++)
#pragma unroll
        for (int ni = 0; ni < 4; ni++)
#pragma unroll
            for (int q = 0; q < 4; q++) c[mi][ni][q] = 0.f;

    prefetch_stage(sb, A_g, B_g, 0, tid);
    CP_COMMIT();

    for (int kc = 0; kc < NCHUNK; kc++) {
        const uint32_t st = sb + (uint32_t)(kc & 1) * STAGE_BYTES;
        if (kc + 1 < NCHUNK) {
            prefetch_stage(sb + (uint32_t)((kc + 1) & 1) * STAGE_BYTES,
                           A_g, B_g, (kc + 1) * KC, tid);
            CP_COMMIT();
            CP_WAIT(1);
        } else {
            CP_WAIT(0);
        }
        __syncthreads();

        const uint32_t sA = st;
        const uint32_t sB = st + TILE_BYTES;

#pragma unroll
        for (int ks = 0; ks < NKSTEP; ks++) {
            const uint32_t koff = (uint32_t)(ks * 32 + ((lid >> 4) << 4));

            uint32_t a[4][4];
#pragma unroll
            for (int mi = 0; mi < 4; mi++) {
                int row = warp_m * 64 + mi * 16 + (lid & 15);
                ldsm_x4(sA + sw128((uint32_t)(row * 128) + koff), a[mi]);
            }

            uint32_t b[4][2];
#pragma unroll
            for (int nb = 0; nb < 2; nb++) {
                int row = warp_n * 32 + nb * 16 + (lid & 15);
                uint32_t r[4];
                ldsm_x4(sB + sw128((uint32_t)(row * 128) + koff), r);
                b[nb * 2][0] = r[0]; b[nb * 2][1] = r[2];
                b[nb * 2 + 1][0] = r[1]; b[nb * 2 + 1][1] = r[3];
            }

#pragma unroll
            for (int mi = 0; mi < 4; mi++)
#pragma unroll
                for (int ni = 0; ni < 4; ni++)
                    mma_f16(c[mi][ni], a[mi], b[ni]);
        }
        __syncthreads();
    }

    // clamp once
#pragma unroll
    for (int mi = 0; mi < 4; mi++)
#pragma unroll
        for (int ni = 0; ni < 4; ni++)
#pragma unroll
            for (int q = 0; q < 4; q++) c[mi][ni][q] = fmaxf(c[mi][ni][q], 0.f);

    // ---- epilogue 1: direct store of tile (tm, tn) ----
    const int rr0 = warp_m * 64 + (lid >> 2);       // row within tile
    const int cc0 = warp_n * 32 + (lid & 3) * 2;    // col within tile
    {
        const int row0 = tile_m * TM + rr0;
        const int col0 = tile_n * TN + cc0;
#pragma unroll
        for (int mi = 0; mi < 4; mi++) {
            float* r0p = out + (size_t)(row0 + mi * 16) * NROWS + col0;
            float* r1p = out + (size_t)(row0 + mi * 16 + 8) * NROWS + col0;
#pragma unroll
            for (int ni = 0; ni < 4; ni++)
                *(float2*)(r0p + ni * 8) = make_float2(c[mi][ni][0], c[mi][ni][1]);
#pragma unroll
            for (int ni = 0; ni < 4; ni++)
                *(float2*)(r1p + ni * 8) = make_float2(c[mi][ni][2], c[mi][ni][3]);
        }
    }

    // ---- epilogue 2: mirrored tile (tn, tm), two 64-col transpose chunks ----
    if (tile_n != tile_m) {
        float* smem_t = (float*)smem;   // 64 x TPITCH floats (33.8 KB)
        const size_t obase = (size_t)tile_n * TN * NROWS + (size_t)tile_m * TM;

#pragma unroll
        for (int ch = 0; ch < 2; ch++) {
            __syncthreads();
            if ((warp_n >> 1) == ch) {           // warps owning cols [64*ch, 64*ch+64)
                const int lc0 = cc0 - ch * 64;   // 0..62
#pragma unroll
                for (int mi = 0; mi < 4; mi++) {
                    const int rA = rr0 + mi * 16;
                    const int rB = rA + 8;
#pragma unroll
                    for (int ni = 0; ni < 4; ni++) {
                        const int lc = lc0 + ni * 8;
                        smem_t[(lc)     * TPITCH + rA] = c[mi][ni][0];
                        smem_t[(lc + 1) * TPITCH + rA] = c[mi][ni][1];
                        smem_t[(lc)     * TPITCH + rB] = c[mi][ni][2];
                        smem_t[(lc + 1) * TPITCH + rB] = c[mi][ni][3];
                    }
                }
            }
            __syncthreads();

            // copy out 64 transposed rows x 128 cols, coalesced float4
#pragma unroll
            for (int j = 0; j < 8; j++) {
                int v = tid + j * 256;            // 0..2047 float4 units
                int cc = v >> 5;                  // 0..63 local transposed row
                int r4 = (v & 31) * 4;            // 0..124
                float4 val = *(const float4*)(smem_t + cc * TPITCH + r4);
                *(float4*)(out + obase + (size_t)(ch * 64 + cc) * NROWS + r4) = val;
            }
        }
    }
}

// ============================================================================
// Launch
// ============================================================================
extern "C" void kernel_launch(void* const* d_in, const int* in_sizes, int n_in,
                              void* d_out, int out_size) {
    const float* features = (const float*)d_in[0];
    float* out = (float*)d_out;

    norm_kernel<<<NROWS / 8, 256>>>(features);

    cudaFuncSetAttribute(gram_mma_kernel,
                         cudaFuncAttributeMaxDynamicSharedMemorySize, SMEM_TOTAL);
    gram_mma_kernel<<<NCTAS, 256, SMEM_TOTAL>>>(out);
}